// round 7
// baseline (speedup 1.0000x reference)
#include <cuda_runtime.h>
#include <cstdint>

// LinearTimeMMD, TMA-pipelined persistent kernel.
// source/target [65536, 512] fp32 -> scalar. m2 = 32768 pairs.
// 296 persistent blocks x 128 threads. Chunk = 4 pairs (8 rows) per tensor,
// staged 32KB at a time into a 3-deep smem ring via cp.async.bulk + mbarrier.
// Warp-per-pair consumers (LDS.128), parallel-exp epilogue, fixed-point
// int64 atomic finish.

#define M2              32768
#define THREADS         128
#define WARPS           4
#define GRID            296
#define STAGES          3
#define PAIRS_PER_CHUNK 4
#define CHUNKS          (M2 / PAIRS_PER_CHUNK)      // 8192
#define CHUNK_FLOATS    (8 * 512)                    // 8 rows = 4096 floats = 16KB
#define STAGE_FLOATS    (2 * CHUNK_FLOATS)           // src+tgt = 8192 floats = 32KB
#define STAGE_BYTES     (STAGE_FLOATS * 4)           // 32768
#define SMEM_DYN_BYTES  (STAGES * STAGE_BYTES)       // 98304

// 2^40 fixed-point scale: |h| <= 10 per pair; block sum < 2^48; total < 2^59.
#define FP_SCALE        1099511627776.0

__device__ long long    g_acc   = 0;
__device__ unsigned int g_count = 0;

__device__ __forceinline__ uint32_t smem_u32(const void* p) {
    return (uint32_t)__cvta_generic_to_shared(p);
}
__device__ __forceinline__ void mbar_init(uint32_t a, uint32_t cnt) {
    asm volatile("mbarrier.init.shared.b64 [%0], %1;" :: "r"(a), "r"(cnt) : "memory");
}
__device__ __forceinline__ void mbar_expect_tx(uint32_t a, uint32_t bytes) {
    asm volatile("mbarrier.arrive.expect_tx.shared.b64 _, [%0], %1;"
                 :: "r"(a), "r"(bytes) : "memory");
}
__device__ __forceinline__ void mbar_arrive(uint32_t a) {
    asm volatile("mbarrier.arrive.shared.b64 _, [%0];" :: "r"(a) : "memory");
}
__device__ __forceinline__ void mbar_wait(uint32_t a, uint32_t parity) {
    asm volatile(
        "{\n\t"
        ".reg .pred P;\n\t"
        "WAIT_%=:\n\t"
        "mbarrier.try_wait.parity.acquire.cta.shared::cta.b64 P, [%0], %1, 0x989680;\n\t"
        "@P bra DONE_%=;\n\t"
        "bra WAIT_%=;\n\t"
        "DONE_%=:\n\t"
        "}" :: "r"(a), "r"(parity) : "memory");
}
__device__ __forceinline__ void bulk_g2s(uint32_t dst, const void* src,
                                         uint32_t bytes, uint32_t mbar) {
    asm volatile(
        "cp.async.bulk.shared::cta.global.mbarrier::complete_tx::bytes [%0], [%1], %2, [%3];"
        :: "r"(dst), "l"(src), "r"(bytes), "r"(mbar) : "memory");
}

__global__ __launch_bounds__(THREADS)
void mmd_tma_kernel(const float* __restrict__ src,
                    const float* __restrict__ tgt,
                    float* __restrict__ out)
{
    extern __shared__ float s_data[];          // STAGES * STAGE_FLOATS
    __shared__ uint64_t  s_full[STAGES];
    __shared__ uint64_t  s_empty[STAGES];
    __shared__ long long s_h[WARPS];

    const int t   = threadIdx.x;
    const int wid = t >> 5;
    const int lid = t & 31;
    const int b   = blockIdx.x;

    uint32_t full_a[STAGES], empty_a[STAGES], data_a[STAGES];
    #pragma unroll
    for (int s = 0; s < STAGES; ++s) {
        full_a[s]  = smem_u32(&s_full[s]);
        empty_a[s] = smem_u32(&s_empty[s]);
        data_a[s]  = smem_u32(s_data + s * STAGE_FLOATS);
    }

    if (t == 0) {
        #pragma unroll
        for (int s = 0; s < STAGES; ++s) {
            mbar_init(full_a[s], 1);        // producer expect_tx arrival
            mbar_init(empty_a[s], WARPS);   // one arrival per consumer warp
        }
        asm volatile("fence.proxy.async.shared::cta;" ::: "memory");
    }
    __syncthreads();

    // this block's chunks: c_i = b + i*GRID
    const int n = (CHUNKS - b + GRID - 1) / GRID;   // 27 or 28

    // prologue: prefetch first STAGES chunks
    if (t == 0) {
        #pragma unroll
        for (int s = 0; s < STAGES; ++s) {
            if (s < n) {
                const int c = b + s * GRID;
                mbar_expect_tx(full_a[s], STAGE_BYTES);
                bulk_g2s(data_a[s],                      src + (size_t)c * CHUNK_FLOATS,
                         CHUNK_FLOATS * 4, full_a[s]);
                bulk_g2s(data_a[s] + CHUNK_FLOATS * 4,   tgt + (size_t)c * CHUNK_FLOATS,
                         CHUNK_FLOATS * 4, full_a[s]);
            }
        }
    }

    // per-lane epilogue constants (lanes 0..19 active)
    const int   term  = lid & 3;                  // 0:dxx 1:dyy 2:dxy 3:dyx
    const float mult  = (float)(1 << (lid >> 2)); // 2^k
    const float signf = (term >= 2) ? -1.f : 1.f;
    float hacc = 0.f;

    int stage = 0, phase = 0;
    for (int i = 0; i < n; ++i) {
        mbar_wait(full_a[stage], phase);

        const float4* stp = (const float4*)s_data + (size_t)stage * (STAGE_FLOATS / 4);
        const float4* sA = stp + (2 * wid)     * 128;          // src row 2w
        const float4* sB = stp + (2 * wid + 1) * 128;          // src row 2w+1
        const float4* tA = stp + (STAGE_FLOATS / 8) + (2 * wid)     * 128;  // tgt row 2w
        const float4* tB = stp + (STAGE_FLOATS / 8) + (2 * wid + 1) * 128;  // tgt row 2w+1

        float dxx = 0.f, dyy = 0.f, dxy = 0.f, dyx = 0.f;
        #pragma unroll
        for (int k = 0; k < 4; ++k) {
            const int c4 = lid + 32 * k;
            const float4 xo = sA[c4];
            const float4 xe = sB[c4];
            const float4 yo = tA[c4];
            const float4 ye = tB[c4];
            float d;
            d = xo.x - xe.x; dxx = fmaf(d, d, dxx);
            d = xo.y - xe.y; dxx = fmaf(d, d, dxx);
            d = xo.z - xe.z; dxx = fmaf(d, d, dxx);
            d = xo.w - xe.w; dxx = fmaf(d, d, dxx);

            d = yo.x - ye.x; dyy = fmaf(d, d, dyy);
            d = yo.y - ye.y; dyy = fmaf(d, d, dyy);
            d = yo.z - ye.z; dyy = fmaf(d, d, dyy);
            d = yo.w - ye.w; dyy = fmaf(d, d, dyy);

            d = xo.x - ye.x; dxy = fmaf(d, d, dxy);
            d = xo.y - ye.y; dxy = fmaf(d, d, dxy);
            d = xo.z - ye.z; dxy = fmaf(d, d, dxy);
            d = xo.w - ye.w; dxy = fmaf(d, d, dxy);

            d = xe.x - yo.x; dyx = fmaf(d, d, dyx);
            d = xe.y - yo.y; dyx = fmaf(d, d, dyx);
            d = xe.z - yo.z; dyx = fmaf(d, d, dyx);
            d = xe.w - yo.w; dyx = fmaf(d, d, dyx);
        }

        // warp tree reduce (4 values) -> all lanes hold totals
        #pragma unroll
        for (int off = 16; off > 0; off >>= 1) {
            dxx += __shfl_xor_sync(0xffffffffu, dxx, off);
            dyy += __shfl_xor_sync(0xffffffffu, dyy, off);
            dxy += __shfl_xor_sync(0xffffffffu, dxy, off);
            dyx += __shfl_xor_sync(0xffffffffu, dyx, off);
        }

        // parallel epilogue: lanes 0..19 each add one signed exp term
        if (lid < 20) {
            const float bw  = (dxx + dyy + dxy + dyx) * (1.0f / 16.0f);
            const float inv = 1.0f / (bw * mult + 1e-6f);
            const float dsel = (term == 0) ? dxx : (term == 1) ? dyy
                             : (term == 2) ? dxy : dyx;
            hacc = fmaf(signf, expf(-dsel * inv), hacc);
        }

        // stage fully consumed by this warp
        if (lid == 0) mbar_arrive(empty_a[stage]);

        // producer refill: wait all 4 warps done with this slot, reissue
        if (t == 0 && i + STAGES < n) {
            mbar_wait(empty_a[stage], phase);
            const int c = b + (i + STAGES) * GRID;
            mbar_expect_tx(full_a[stage], STAGE_BYTES);
            bulk_g2s(data_a[stage],                    src + (size_t)c * CHUNK_FLOATS,
                     CHUNK_FLOATS * 4, full_a[stage]);
            bulk_g2s(data_a[stage] + CHUNK_FLOATS * 4, tgt + (size_t)c * CHUNK_FLOATS,
                     CHUNK_FLOATS * 4, full_a[stage]);
        }

        if (++stage == STAGES) { stage = 0; phase ^= 1; }
    }

    // final warp reduce of h across lanes
    #pragma unroll
    for (int off = 16; off > 0; off >>= 1)
        hacc += __shfl_xor_sync(0xffffffffu, hacc, off);

    if (lid == 0)
        s_h[wid] = (long long)llrint((double)hacc * FP_SCALE);
    __syncthreads();

    if (t == 0) {
        long long v = 0;
        #pragma unroll
        for (int w = 0; w < WARPS; ++w) v += s_h[w];
        atomicAdd((unsigned long long*)&g_acc, (unsigned long long)v);

        __threadfence();
        unsigned int done = atomicAdd(&g_count, 1u);
        if (done == GRID - 1) {
            __threadfence();   // acquire: all other blocks' adds visible
            long long acc = g_acc;
            out[0] = (float)(((double)acc / FP_SCALE) / (double)M2);
            g_acc   = 0;       // reset for next graph replay
            g_count = 0;
            __threadfence();
        }
    }
}

extern "C" void kernel_launch(void* const* d_in, const int* in_sizes, int n_in,
                              void* d_out, int out_size)
{
    const float* src = (const float*)d_in[0];
    const float* tgt = (const float*)d_in[1];
    float* out = (float*)d_out;

    cudaFuncSetAttribute(mmd_tma_kernel,
                         cudaFuncAttributeMaxDynamicSharedMemorySize,
                         SMEM_DYN_BYTES);
    mmd_tma_kernel<<<GRID, THREADS, SMEM_DYN_BYTES>>>(src, tgt, out);
}

// round 8
// speedup vs baseline: 1.0543x; 1.0543x over previous
#include <cuda_runtime.h>

// LinearTimeMMD fused: source/target [65536, 512] fp32 -> scalar.
// R4 geometry (best: 75.6% DRAM): warp-per-pair, 4 chunks of 4 float4 with
// immediate accumulation, __launch_bounds__(256,8) -> 64 warps/SM.
// R8 refinement: parallel-exp epilogue (lanes 0..19, one signed exp each)
// replaces the serial 20-exp chain on lane 0.
// 8 pairs per 256-thread block; one fixed-point int64 atomic per block.

#define M2            32768
#define PAIRS_PER_BLK 8
#define THREADS       256
#define GRID          (M2 / PAIRS_PER_BLK)   // 4096
#define F4_PER_ROW    128                    // 512 floats / 4

// 2^40 fixed-point scale: |h| <= 10 -> |v| < 2^44; sum over 32768 < 2^59.
#define FP_SCALE      1099511627776.0

__device__ long long    g_acc   = 0;
__device__ unsigned int g_count = 0;

__global__ __launch_bounds__(THREADS, 8)
void mmd_fused_kernel(const float4* __restrict__ src,
                      const float4* __restrict__ tgt,
                      float* __restrict__ out)
{
    const int t   = threadIdx.x;
    const int wid = t >> 5;                 // warp id in block = pair slot
    const int lid = t & 31;
    const int p   = blockIdx.x * PAIRS_PER_BLK + wid;

    const size_t ro = (size_t)(2 * p) * F4_PER_ROW;      // row 2p
    const size_t re = ro + F4_PER_ROW;                   // row 2p+1

    float dxx = 0.f, dyy = 0.f, dxy = 0.f, dyx = 0.f;

    #pragma unroll
    for (int k = 0; k < 4; ++k) {
        const int c = lid + 32 * k;
        const float4 xo = __ldcs(src + ro + c);
        const float4 xe = __ldcs(src + re + c);
        const float4 yo = __ldcs(tgt + ro + c);
        const float4 ye = __ldcs(tgt + re + c);

        float d;
        d = xo.x - xe.x; dxx = fmaf(d, d, dxx);
        d = xo.y - xe.y; dxx = fmaf(d, d, dxx);
        d = xo.z - xe.z; dxx = fmaf(d, d, dxx);
        d = xo.w - xe.w; dxx = fmaf(d, d, dxx);

        d = yo.x - ye.x; dyy = fmaf(d, d, dyy);
        d = yo.y - ye.y; dyy = fmaf(d, d, dyy);
        d = yo.z - ye.z; dyy = fmaf(d, d, dyy);
        d = yo.w - ye.w; dyy = fmaf(d, d, dyy);

        d = xo.x - ye.x; dxy = fmaf(d, d, dxy);
        d = xo.y - ye.y; dxy = fmaf(d, d, dxy);
        d = xo.z - ye.z; dxy = fmaf(d, d, dxy);
        d = xo.w - ye.w; dxy = fmaf(d, d, dxy);

        d = xe.x - yo.x; dyx = fmaf(d, d, dyx);
        d = xe.y - yo.y; dyx = fmaf(d, d, dyx);
        d = xe.z - yo.z; dyx = fmaf(d, d, dyx);
        d = xe.w - yo.w; dyx = fmaf(d, d, dyx);
    }

    // warp tree reduce (4 values) -> all lanes hold the totals
    #pragma unroll
    for (int off = 16; off > 0; off >>= 1) {
        dxx += __shfl_xor_sync(0xffffffffu, dxx, off);
        dyy += __shfl_xor_sync(0xffffffffu, dyy, off);
        dxy += __shfl_xor_sync(0xffffffffu, dxy, off);
        dyx += __shfl_xor_sync(0xffffffffu, dyx, off);
    }

    // parallel epilogue: lanes 0..19 each compute one signed exp term
    //   kernel index k = lid>>2 (mult = 2^k), term = lid&3
    float h = 0.f;
    if (lid < 20) {
        const int   term = lid & 3;
        const float mult = (float)(1 << (lid >> 2));
        const float bw   = (dxx + dyy + dxy + dyx) * (1.0f / 16.0f);
        const float inv  = 1.0f / (bw * mult + 1e-6f);
        const float dsel = (term == 0) ? dxx : (term == 1) ? dyy
                         : (term == 2) ? dxy : dyx;
        h = expf(-dsel * inv);
        if (term >= 2) h = -h;
    }
    #pragma unroll
    for (int off = 16; off > 0; off >>= 1)
        h += __shfl_xor_sync(0xffffffffu, h, off);

    __shared__ long long h_fixed[PAIRS_PER_BLK];
    if (lid == 0)
        h_fixed[wid] = (long long)llrint((double)h * FP_SCALE);
    __syncthreads();

    if (t == 0) {
        long long v = 0;
        #pragma unroll
        for (int w = 0; w < PAIRS_PER_BLK; ++w) v += h_fixed[w];
        atomicAdd((unsigned long long*)&g_acc, (unsigned long long)v);

        __threadfence();
        unsigned int done = atomicAdd(&g_count, 1u);
        if (done == GRID - 1) {
            __threadfence();   // acquire: all other blocks' adds visible
            long long acc = g_acc;
            out[0] = (float)(((double)acc / FP_SCALE) / (double)M2);
            // reset for next graph replay
            g_acc   = 0;
            g_count = 0;
            __threadfence();
        }
    }
}

extern "C" void kernel_launch(void* const* d_in, const int* in_sizes, int n_in,
                              void* d_out, int out_size)
{
    const float4* src = (const float4*)d_in[0];
    const float4* tgt = (const float4*)d_in[1];
    float* out = (float*)d_out;

    mmd_fused_kernel<<<GRID, THREADS>>>(src, tgt, out);
}